// round 5
// baseline (speedup 1.0000x reference)
#include <cuda_runtime.h>

#define OMEGA 30.0f
#define P_TOTAL 50177
#define P_STRIDE 50192       // padded to multiple of 16 floats -> 16B-aligned bases
#define BATCH 16
#define N_PTS 32768
#define TILE_P 32            // points per tile
#define TILES_PER_CTA 8
#define CTAS_Y 128           // CTAS_Y * TILES_PER_CTA * TILE_P = 32768

// Param layout per batch (after permutation): W0[128x3]@0, b0@384, W1t[k][n]@512,
// b1@16896, W2t@17024, b2@33408, W3t@33536, b3@49920, Wo@50048, bo@50176
#define OFF_W1 512
#define OFF_B1 16896
#define OFF_W2 17024
#define OFF_B2 33408
#define OFF_W3 33536
#define OFF_B3 49920
#define OFF_WO 50048
#define OFF_BO 50176

__device__ float g_h2[BATCH * 256];
__device__ __align__(16) float g_params[BATCH * P_STRIDE];

// ---------------------------------------------------------------------------
// Packed fp32x2 helpers (Blackwell sm_100a)
// ---------------------------------------------------------------------------
__device__ __forceinline__ void ffma2(unsigned long long& d,
                                      unsigned long long a,
                                      unsigned long long b) {
    asm("fma.rn.f32x2 %0, %1, %2, %0;" : "+l"(d) : "l"(a), "l"(b));
}
__device__ __forceinline__ unsigned long long pack2(float x, float y) {
    unsigned long long r;
    asm("mov.b64 %0, {%1, %2};" : "=l"(r) : "f"(x), "f"(y));
    return r;
}
__device__ __forceinline__ float2 unpack2(unsigned long long v) {
    float2 r;
    asm("mov.b64 {%0, %1}, %2;" : "=f"(r.x), "=f"(r.y) : "l"(v));
    return r;
}

// ---------------------------------------------------------------------------
// K1: hypernet hidden chain. One CTA per sample, 256 threads (one per neuron).
// ---------------------------------------------------------------------------
__global__ void __launch_bounds__(256) hyper_hidden_kernel(
    const float* __restrict__ t,
    const float* __restrict__ hW0, const float* __restrict__ hb0,
    const float* __restrict__ hW1, const float* __restrict__ hb1,
    const float* __restrict__ hW2, const float* __restrict__ hb2) {
    __shared__ float ts[8];
    __shared__ float h0[256];
    __shared__ float h1[256];
    int b = blockIdx.x;
    int n = threadIdx.x;
    if (n < 8) ts[n] = t[b * 8 + n];
    __syncthreads();

    float acc = hb0[n];
#pragma unroll
    for (int i = 0; i < 8; i++) acc += ts[i] * hW0[n * 8 + i];
    h0[n] = sinf(OMEGA * acc);  // accurate sinf: args can reach ~±25 here
    __syncthreads();

    acc = hb1[n];
#pragma unroll 8
    for (int c = 0; c < 256; c++) acc += h0[c] * hW1[n * 256 + c];
    h1[n] = sinf(OMEGA * acc);
    __syncthreads();

    acc = hb2[n];
#pragma unroll 8
    for (int c = 0; c < 256; c++) acc += h1[c] * hW2[n * 256 + c];
    g_h2[b * 256 + n] = sinf(OMEGA * acc);
}

// ---------------------------------------------------------------------------
// K2: params[b][j] = h2[b] . hWo[j] + hbo[j], written with W1/W2/W3 transposed
// ([out][in] -> [in][out]) so the INR kernel copies straight into SMEM.
// ---------------------------------------------------------------------------
__device__ __forceinline__ int permute_idx(int j) {
    if (j < OFF_W1) return j;
    if (j < OFF_B1) { int r = j - OFF_W1; return OFF_W1 + (r & 127) * 128 + (r >> 7); }
    if (j < OFF_W2) return j;
    if (j < OFF_B2) { int r = j - OFF_W2; return OFF_W2 + (r & 127) * 128 + (r >> 7); }
    if (j < OFF_W3) return j;
    if (j < OFF_B3) { int r = j - OFF_W3; return OFF_W3 + (r & 127) * 128 + (r >> 7); }
    return j;
}

__global__ void __launch_bounds__(256) hyper_out_kernel(
    const float* __restrict__ hWo, const float* __restrict__ hbo) {
    __shared__ float h2s[BATCH * 256];
    int tid = threadIdx.x;
    for (int i = tid; i < BATCH * 256; i += 256) h2s[i] = g_h2[i];
    __syncthreads();

    int j = blockIdx.x * 256 + tid;
    if (j >= P_TOTAL) return;

    float bias = hbo[j];
    float acc[BATCH];
#pragma unroll
    for (int b = 0; b < BATCH; b++) acc[b] = bias;

    const float4* w4 = reinterpret_cast<const float4*>(hWo + (size_t)j * 256);
#pragma unroll 4
    for (int c4 = 0; c4 < 64; c4++) {
        float4 w = w4[c4];
#pragma unroll
        for (int b = 0; b < BATCH; b++) {
            float4 h = *reinterpret_cast<const float4*>(&h2s[b * 256 + c4 * 4]);
            acc[b] += w.x * h.x + w.y * h.y + w.z * h.z + w.w * h.w;
        }
    }
    int dest = permute_idx(j);
#pragma unroll
    for (int b = 0; b < BATCH; b++) g_params[(size_t)b * P_STRIDE + dest] = acc[b];
}

// ---------------------------------------------------------------------------
// K3: INR evaluation. 256 threads/CTA; thread = (px, ny): 2 points x 8 neurons.
// SMEM: W1t/W2t/W3t [128][128] + act ping-pong [128][TILE_P] x2 = 229376 B.
// Activations stored k-major: act[k * TILE_P + p].
// ---------------------------------------------------------------------------
__device__ __forceinline__ void hidden_layer(
    const float* __restrict__ aIn, float* __restrict__ aOut,
    const float* __restrict__ W,  const float* __restrict__ bias,
    int px, int nbase) {
    unsigned long long acc0[4], acc1[4];  // [neuron-pair], point 0 / point 1
    unsigned long long z = pack2(0.f, 0.f);
#pragma unroll
    for (int q = 0; q < 4; q++) { acc0[q] = z; acc1[q] = z; }

#pragma unroll 8
    for (int k = 0; k < 128; k++) {
        float2 h = *reinterpret_cast<const float2*>(&aIn[k * TILE_P + 2 * px]);
        unsigned long long hh0 = pack2(h.x, h.x);
        unsigned long long hh1 = pack2(h.y, h.y);
        const ulonglong2* wrow =
            reinterpret_cast<const ulonglong2*>(&W[k * 128 + nbase]);
        ulonglong2 wa = wrow[0];  // neurons nbase..nbase+3 (2 packed pairs)
        ulonglong2 wb = wrow[1];  // neurons nbase+4..nbase+7
        ffma2(acc0[0], hh0, wa.x); ffma2(acc1[0], hh1, wa.x);
        ffma2(acc0[1], hh0, wa.y); ffma2(acc1[1], hh1, wa.y);
        ffma2(acc0[2], hh0, wb.x); ffma2(acc1[2], hh1, wb.x);
        ffma2(acc0[3], hh0, wb.y); ffma2(acc1[3], hh1, wb.y);
    }

#pragma unroll
    for (int q = 0; q < 4; q++) {
        float2 e0 = unpack2(acc0[q]);  // point 0: neurons (nbase+2q, nbase+2q+1)
        float2 e1 = unpack2(acc1[q]);  // point 1
        float b0 = __ldg(&bias[nbase + 2 * q]);
        float b1 = __ldg(&bias[nbase + 2 * q + 1]);
        float2 v_even, v_odd;
        v_even.x = __sinf(OMEGA * (e0.x + b0));
        v_even.y = __sinf(OMEGA * (e1.x + b0));
        v_odd.x  = __sinf(OMEGA * (e0.y + b1));
        v_odd.y  = __sinf(OMEGA * (e1.y + b1));
        *reinterpret_cast<float2*>(&aOut[(nbase + 2 * q) * TILE_P + 2 * px]) = v_even;
        *reinterpret_cast<float2*>(&aOut[(nbase + 2 * q + 1) * TILE_P + 2 * px]) = v_odd;
    }
}

__global__ void __launch_bounds__(256, 1) inr_kernel(
    const float* __restrict__ xt, float* __restrict__ out) {
    extern __shared__ float sm[];
    float* sW1  = sm;
    float* sW2  = sm + 16384;
    float* sW3  = sm + 32768;
    float* actA = sm + 49152;
    float* actB = sm + 53248;

    int b   = blockIdx.x;
    int tid = threadIdx.x;
    const float* p = g_params + (size_t)b * P_STRIDE;

    // Coalesced copy of the three pre-transposed hidden matrices into SMEM.
    // p is 16B-aligned (P_STRIDE % 4 == 0) and OFF_W* are multiples of 4.
    {
        const float4* s1 = reinterpret_cast<const float4*>(p + OFF_W1);
        const float4* s2 = reinterpret_cast<const float4*>(p + OFF_W2);
        const float4* s3 = reinterpret_cast<const float4*>(p + OFF_W3);
        float4* d1 = reinterpret_cast<float4*>(sW1);
        float4* d2 = reinterpret_cast<float4*>(sW2);
        float4* d3 = reinterpret_cast<float4*>(sW3);
        for (int i = tid; i < 4096; i += 256) {
            d1[i] = s1[i]; d2[i] = s2[i]; d3[i] = s3[i];
        }
    }
    __syncthreads();

    int px = tid & 15;         // point group: points {2px, 2px+1}
    int ny = tid >> 4;         // neuron group
    int nbase = ny * 8;

    for (int tile = 0; tile < TILES_PER_CTA; tile++) {
        int pbase = blockIdx.y * (TILES_PER_CTA * TILE_P) + tile * TILE_P;

        // ---- layer 0: in=3 (read xt + W0/b0 straight from L1-cached gmem)
        {
            float h[2][8];
#pragma unroll
            for (int pp = 0; pp < 2; pp++) {
                int pnt = pbase + 2 * px + pp;
                const float* x3 = xt + ((size_t)b * N_PTS + pnt) * 3;
                float x = x3[0], y = x3[1], z = x3[2];
#pragma unroll
                for (int jj = 0; jj < 8; jj++) {
                    int n = nbase + jj;
                    float a = __ldg(&p[n * 3 + 0]) * x
                            + __ldg(&p[n * 3 + 1]) * y
                            + __ldg(&p[n * 3 + 2]) * z
                            + __ldg(&p[384 + n]);
                    h[pp][jj] = __sinf(OMEGA * a);
                }
            }
#pragma unroll
            for (int jj = 0; jj < 8; jj++) {
                float2 v = make_float2(h[0][jj], h[1][jj]);
                *reinterpret_cast<float2*>(
                    &actA[(nbase + jj) * TILE_P + 2 * px]) = v;
            }
        }
        __syncthreads();

        // ---- hidden layers 1..3
        hidden_layer(actA, actB, sW1, p + OFF_B1, px, nbase);
        __syncthreads();
        hidden_layer(actB, actA, sW2, p + OFF_B2, px, nbase);
        __syncthreads();
        hidden_layer(actA, actB, sW3, p + OFF_B3, px, nbase);
        __syncthreads();

        // ---- output layer: y[p] = sum_k actB[k][p] * Wo[k] + bo
        {
            int pl  = tid >> 3;   // 0..31 point within tile
            int seg = tid & 7;    // k segment
            float partial = 0.f;
#pragma unroll
            for (int kk = 0; kk < 16; kk++) {
                int k = seg * 16 + kk;
                partial += actB[k * TILE_P + pl] * __ldg(&p[OFF_WO + k]);
            }
            partial += __shfl_xor_sync(0xffffffffu, partial, 1);
            partial += __shfl_xor_sync(0xffffffffu, partial, 2);
            partial += __shfl_xor_sync(0xffffffffu, partial, 4);
            if (seg == 0) {
                out[(size_t)b * N_PTS + pbase + pl] = partial + __ldg(&p[OFF_BO]);
            }
        }
        __syncthreads();
    }
}

// ---------------------------------------------------------------------------
extern "C" void kernel_launch(void* const* d_in, const int* in_sizes, int n_in,
                              void* d_out, int out_size) {
    const float* t   = (const float*)d_in[0];
    const float* xt  = (const float*)d_in[1];
    const float* hW0 = (const float*)d_in[2];
    const float* hb0 = (const float*)d_in[3];
    const float* hW1 = (const float*)d_in[4];
    const float* hb1 = (const float*)d_in[5];
    const float* hW2 = (const float*)d_in[6];
    const float* hb2 = (const float*)d_in[7];
    const float* hWo = (const float*)d_in[8];
    const float* hbo = (const float*)d_in[9];
    float* out = (float*)d_out;

    hyper_hidden_kernel<<<BATCH, 256>>>(t, hW0, hb0, hW1, hb1, hW2, hb2);
    hyper_out_kernel<<<(P_TOTAL + 255) / 256, 256>>>(hWo, hbo);

    const int smem_bytes = (3 * 16384 + 2 * 128 * TILE_P) * (int)sizeof(float);
    cudaFuncSetAttribute(inr_kernel,
                         cudaFuncAttributeMaxDynamicSharedMemorySize, smem_bytes);
    inr_kernel<<<dim3(BATCH, CTAS_Y), 256, smem_bytes>>>(xt, out);
}

// round 7
// speedup vs baseline: 2.4935x; 2.4935x over previous
#include <cuda_runtime.h>
#include <cuda_bf16.h>
#include <cstdint>

#define OMEGA 30.0f
#define P_TOTAL 50177
#define BATCH 16
#define N_PTS 32768
#define TILES_PER_CTA 4
#define CTAS_Y 64             // 64 * 4 * 128 = 32768 points per batch

#define WS 136                // padded K stride (bf16 elems) -> conflict-free LDS
#define MS (128 * WS)         // 17408 elems per matrix

// small params per batch: W0[384]@0 b0@384 b1@512 b2@640 b3@768 Wo@896 bo@1024
__device__ __align__(16) float g_h2[BATCH * 256];
__device__ __align__(16) float g_small[BATCH][1040];
// per batch: W1hi W1lo W2hi W2lo W3hi W3lo, each [n][k] row-major, stride WS
__device__ __align__(16) unsigned short g_wblk[BATCH][6 * MS];

#define SM_SMALL (6 * MS * 2)              // 208896
#define SMEM_TOTAL (SM_SMALL + 1040 * 4)   // 213056

// ---------------------------------------------------------------------------
// helpers
// ---------------------------------------------------------------------------
__device__ __forceinline__ uint32_t smem_u32(const void* p) {
    uint32_t a;
    asm("{ .reg .u64 t; cvta.to.shared.u64 t, %1; cvt.u32.u64 %0, t; }"
        : "=r"(a) : "l"(p));
    return a;
}
__device__ __forceinline__ uint32_t lds32(uint32_t a) {
    uint32_t v;
    asm volatile("ld.shared.b32 %0, [%1];" : "=r"(v) : "r"(a));
    return v;
}
__device__ __forceinline__ float ldsf(uint32_t a) {
    float v;
    asm volatile("ld.shared.f32 %0, [%1];" : "=f"(v) : "r"(a));
    return v;
}
__device__ __forceinline__ float2 lds2f(uint32_t a) {
    float2 v;
    asm volatile("ld.shared.v2.f32 {%0,%1}, [%2];" : "=f"(v.x), "=f"(v.y) : "r"(a));
    return v;
}
// D += A @ B^T, m16n8k16 bf16, fp32 accum (baseline PTX, works on sm_100)
__device__ __forceinline__ void mma_bf16(float* d, const uint32_t* a,
                                         uint32_t b0, uint32_t b1) {
    asm volatile(
        "mma.sync.aligned.m16n8k16.row.col.f32.bf16.bf16.f32 "
        "{%0,%1,%2,%3}, {%4,%5,%6,%7}, {%8,%9}, {%0,%1,%2,%3};"
        : "+f"(d[0]), "+f"(d[1]), "+f"(d[2]), "+f"(d[3])
        : "r"(a[0]), "r"(a[1]), "r"(a[2]), "r"(a[3]), "r"(b0), "r"(b1));
}
// bf16 hi/lo split of two fp32, packed bf16x2 (first value in low half)
__device__ __forceinline__ void split2(float v0, float v1, uint32_t& hi, uint32_t& lo) {
    __nv_bfloat16 h0 = __float2bfloat16(v0), h1 = __float2bfloat16(v1);
    float r0 = v0 - __bfloat162float(h0), r1 = v1 - __bfloat162float(h1);
    __nv_bfloat16 l0 = __float2bfloat16(r0), l1 = __float2bfloat16(r1);
    hi = (uint32_t)__bfloat16_as_ushort(h0) | ((uint32_t)__bfloat16_as_ushort(h1) << 16);
    lo = (uint32_t)__bfloat16_as_ushort(l0) | ((uint32_t)__bfloat16_as_ushort(l1) << 16);
}

// ---------------------------------------------------------------------------
// K1: hypernet hidden chain, 1024 threads, 4 threads/neuron
// ---------------------------------------------------------------------------
__global__ void __launch_bounds__(1024) hyper_hidden_kernel(
    const float* __restrict__ t,
    const float* __restrict__ hW0, const float* __restrict__ hb0,
    const float* __restrict__ hW1, const float* __restrict__ hb1,
    const float* __restrict__ hW2, const float* __restrict__ hb2) {
    __shared__ float ts[8];
    __shared__ float h0[256];
    __shared__ float h1[256];
    int b = blockIdx.x;
    int tid = threadIdx.x;
    if (tid < 8) ts[tid] = t[b * 8 + tid];
    __syncthreads();

    if (tid < 256) {
        float acc = hb0[tid];
#pragma unroll
        for (int i = 0; i < 8; i++) acc += ts[i] * hW0[tid * 8 + i];
        h0[tid] = sinf(OMEGA * acc);
    }
    __syncthreads();

    int n = tid >> 2, part = tid & 3;
    {
        float acc = 0.f;
#pragma unroll 8
        for (int i = 0; i < 64; i++) {
            int c = part + i * 4;
            acc += h0[c] * hW1[n * 256 + c];
        }
        acc += __shfl_xor_sync(0xffffffffu, acc, 1);
        acc += __shfl_xor_sync(0xffffffffu, acc, 2);
        if (part == 0) h1[n] = sinf(OMEGA * (acc + hb1[n]));
    }
    __syncthreads();
    {
        float acc = 0.f;
#pragma unroll 8
        for (int i = 0; i < 64; i++) {
            int c = part + i * 4;
            acc += h1[c] * hW2[n * 256 + c];
        }
        acc += __shfl_xor_sync(0xffffffffu, acc, 1);
        acc += __shfl_xor_sync(0xffffffffu, acc, 2);
        if (part == 0) g_h2[b * 256 + n] = sinf(OMEGA * (acc + hb2[n]));
    }
}

// ---------------------------------------------------------------------------
// K2: params = h2 @ hWo^T + hbo, routed to g_small (fp32) and g_wblk
// (bf16 hi/lo, [n][k] row-major with stride WS)
// ---------------------------------------------------------------------------
__global__ void __launch_bounds__(256) hyper_out_kernel(
    const float* __restrict__ hWo, const float* __restrict__ hbo) {
    __shared__ float h2s[BATCH * 256];
    int tid = threadIdx.x;
    for (int i = tid; i < BATCH * 256; i += 256) h2s[i] = g_h2[i];
    __syncthreads();

    int j = blockIdx.x * 256 + tid;
    if (j >= P_TOTAL) return;

    float bias = hbo[j];
    float acc[BATCH];
#pragma unroll
    for (int b = 0; b < BATCH; b++) acc[b] = bias;

    const float4* w4 = reinterpret_cast<const float4*>(hWo + (size_t)j * 256);
#pragma unroll 4
    for (int c4 = 0; c4 < 64; c4++) {
        float4 w = w4[c4];
#pragma unroll
        for (int b = 0; b < BATCH; b++) {
            float4 h = *reinterpret_cast<const float4*>(&h2s[b * 256 + c4 * 4]);
            acc[b] += w.x * h.x + w.y * h.y + w.z * h.z + w.w * h.w;
        }
    }

    int layer = -1, r = 0, sidx = -1;
    if (j < 512)            sidx = j;                 // W0 + b0
    else if (j < 16896)   { layer = 0; r = j - 512; }
    else if (j < 17024)     sidx = 512 + (j - 16896); // b1
    else if (j < 33408)   { layer = 1; r = j - 17024; }
    else if (j < 33536)     sidx = 640 + (j - 33408); // b2
    else if (j < 49920)   { layer = 2; r = j - 33536; }
    else if (j < 50048)     sidx = 768 + (j - 49920); // b3
    else if (j < 50176)     sidx = 896 + (j - 50048); // Wo
    else                    sidx = 1024;              // bo

    if (layer >= 0) {
        int n = r >> 7, k = r & 127;
        int idx = n * WS + k;
#pragma unroll
        for (int b = 0; b < BATCH; b++) {
            float v = acc[b];
            __nv_bfloat16 h = __float2bfloat16(v);
            __nv_bfloat16 l = __float2bfloat16(v - __bfloat162float(h));
            g_wblk[b][(2 * layer) * MS + idx]     = __bfloat16_as_ushort(h);
            g_wblk[b][(2 * layer + 1) * MS + idx] = __bfloat16_as_ushort(l);
        }
    } else {
#pragma unroll
        for (int b = 0; b < BATCH; b++) g_small[b][sidx] = acc[b];
    }
}

// ---------------------------------------------------------------------------
// K3: warp-level MMA INR. 8 warps/CTA, each warp owns 16 points; activations
// chain through registers (acc fragment == next A fragment layout).
// ---------------------------------------------------------------------------
__global__ void __launch_bounds__(256, 1) inr_mma_kernel(
    const float* __restrict__ xt, float* __restrict__ out) {
    extern __shared__ char smem[];
    const uint32_t smb = smem_u32(smem);
    int tid = threadIdx.x, b = blockIdx.x;

    // weights + small params -> SMEM (linear float4 copy)
    {
        const float4* src = reinterpret_cast<const float4*>(g_wblk[b]);
        float4* dst = reinterpret_cast<float4*>(smem);
        for (int i = tid; i < (6 * MS * 2) / 16; i += 256) dst[i] = src[i];
        const float4* s2 = reinterpret_cast<const float4*>(g_small[b]);
        float4* d2 = reinterpret_cast<float4*>(smem + SM_SMALL);
        for (int i = tid; i < 260; i += 256) d2[i] = s2[i];
    }
    __syncthreads();

    const int lane = tid & 31, warp = tid >> 5;
    const int r = lane >> 2, qc = (lane & 3) * 2;
    const uint32_t smallb = smb + SM_SMALL;
    const uint32_t wrowoff = (uint32_t)(r * WS + qc) * 2;  // byte offset in W row-block

    for (int tile = 0; tile < TILES_PER_CTA; tile++) {
        int pbase = (blockIdx.y * TILES_PER_CTA + tile) * 128 + warp * 16;
        int p0 = pbase + r;
        const float* xp = xt + ((size_t)b * N_PTS + p0) * 3;
        float x0 = xp[0], y0 = xp[1], z0 = xp[2];
        float x1 = xp[24], y1 = xp[25], z1 = xp[26];  // point p0 + 8

        // ---- layer 0: build A fragments (bf16 hi/lo) directly in registers
        uint32_t ahi[8][4], alo[8][4];
#pragma unroll
        for (int i = 0; i < 8; i++) {
#pragma unroll
            for (int h = 0; h < 2; h++) {
                int n0 = 16 * i + 8 * h + qc;
                float wa0 = ldsf(smallb + (n0 * 3 + 0) * 4);
                float wa1 = ldsf(smallb + (n0 * 3 + 1) * 4);
                float wa2 = ldsf(smallb + (n0 * 3 + 2) * 4);
                float ba  = ldsf(smallb + (384 + n0) * 4);
                float wb0 = ldsf(smallb + (n0 * 3 + 3) * 4);
                float wb1 = ldsf(smallb + (n0 * 3 + 4) * 4);
                float wb2 = ldsf(smallb + (n0 * 3 + 5) * 4);
                float bb  = ldsf(smallb + (385 + n0) * 4);
                float vA0 = __sinf(OMEGA * (wa0 * x0 + wa1 * y0 + wa2 * z0 + ba));
                float vB0 = __sinf(OMEGA * (wb0 * x0 + wb1 * y0 + wb2 * z0 + bb));
                float vA1 = __sinf(OMEGA * (wa0 * x1 + wa1 * y1 + wa2 * z1 + ba));
                float vB1 = __sinf(OMEGA * (wb0 * x1 + wb1 * y1 + wb2 * z1 + bb));
                split2(vA0, vB0, ahi[i][2 * h], alo[i][2 * h]);
                split2(vA1, vB1, ahi[i][2 * h + 1], alo[i][2 * h + 1]);
            }
        }

        float part0 = 0.f, part1 = 0.f;
#pragma unroll 1
        for (int L = 0; L < 3; L++) {
            float acc[16][4];
#pragma unroll
            for (int j = 0; j < 16; j++) {
                acc[j][0] = 0.f; acc[j][1] = 0.f; acc[j][2] = 0.f; acc[j][3] = 0.f;
            }
            uint32_t whib = smb + (uint32_t)(2 * L) * (MS * 2) + wrowoff;
            uint32_t wlob = whib + MS * 2;
            // 3 term passes; j innermost => 16-instr dependency distance per acc
#pragma unroll
            for (int pass = 0; pass < 3; pass++) {
                uint32_t wb_ = (pass == 1) ? wlob : whib;
#pragma unroll
                for (int i = 0; i < 8; i++) {
#pragma unroll
                    for (int j = 0; j < 16; j++) {
                        uint32_t addr = wb_ + (uint32_t)(j * 8 * WS + 16 * i) * 2;
                        uint32_t b0 = lds32(addr), b1 = lds32(addr + 16);
                        if (pass == 2) mma_bf16(acc[j], alo[i], b0, b1);
                        else           mma_bf16(acc[j], ahi[i], b0, b1);
                    }
                }
            }

            if (L < 2) {
                // epilogue: bias + sin + hi/lo split -> next-layer A fragments
                uint32_t biasb = smallb + (uint32_t)(512 + 128 * L) * 4;
#pragma unroll
                for (int j = 0; j < 16; j++) {
                    float2 bs = lds2f(biasb + (8 * j + qc) * 4);
                    float s0 = __sinf(OMEGA * (acc[j][0] + bs.x));
                    float s1 = __sinf(OMEGA * (acc[j][1] + bs.y));
                    float s2 = __sinf(OMEGA * (acc[j][2] + bs.x));
                    float s3 = __sinf(OMEGA * (acc[j][3] + bs.y));
                    split2(s0, s1, ahi[j >> 1][(j & 1) * 2], alo[j >> 1][(j & 1) * 2]);
                    split2(s2, s3, ahi[j >> 1][(j & 1) * 2 + 1], alo[j >> 1][(j & 1) * 2 + 1]);
                }
            } else {
                // final epilogue fused with output dot product
                uint32_t biasb = smallb + 768 * 4;
                uint32_t wob   = smallb + 896 * 4;
#pragma unroll
                for (int j = 0; j < 16; j++) {
                    float2 bs = lds2f(biasb + (8 * j + qc) * 4);
                    float2 wo = lds2f(wob + (8 * j + qc) * 4);
                    part0 += __sinf(OMEGA * (acc[j][0] + bs.x)) * wo.x
                           + __sinf(OMEGA * (acc[j][1] + bs.y)) * wo.y;
                    part1 += __sinf(OMEGA * (acc[j][2] + bs.x)) * wo.x
                           + __sinf(OMEGA * (acc[j][3] + bs.y)) * wo.y;
                }
            }
        }

        part0 += __shfl_xor_sync(0xffffffffu, part0, 1);
        part0 += __shfl_xor_sync(0xffffffffu, part0, 2);
        part1 += __shfl_xor_sync(0xffffffffu, part1, 1);
        part1 += __shfl_xor_sync(0xffffffffu, part1, 2);
        if ((lane & 3) == 0) {
            float bo = ldsf(smallb + 1024 * 4);
            out[(size_t)b * N_PTS + p0]     = part0 + bo;
            out[(size_t)b * N_PTS + p0 + 8] = part1 + bo;
        }
    }
}

// ---------------------------------------------------------------------------
extern "C" void kernel_launch(void* const* d_in, const int* in_sizes, int n_in,
                              void* d_out, int out_size) {
    const float* t   = (const float*)d_in[0];
    const float* xt  = (const float*)d_in[1];
    const float* hW0 = (const float*)d_in[2];
    const float* hb0 = (const float*)d_in[3];
    const float* hW1 = (const float*)d_in[4];
    const float* hb1 = (const float*)d_in[5];
    const float* hW2 = (const float*)d_in[6];
    const float* hb2 = (const float*)d_in[7];
    const float* hWo = (const float*)d_in[8];
    const float* hbo = (const float*)d_in[9];
    float* out = (float*)d_out;

    hyper_hidden_kernel<<<BATCH, 1024>>>(t, hW0, hb0, hW1, hb1, hW2, hb2);
    hyper_out_kernel<<<(P_TOTAL + 255) / 256, 256>>>(hWo, hbo);

    cudaFuncSetAttribute(inr_mma_kernel,
                         cudaFuncAttributeMaxDynamicSharedMemorySize, SMEM_TOTAL);
    inr_mma_kernel<<<dim3(BATCH, CTAS_Y), 256, SMEM_TOTAL>>>(xt, out);
}

// round 8
// speedup vs baseline: 4.3021x; 1.7253x over previous
#include <cuda_runtime.h>
#include <cuda_fp16.h>
#include <cstdint>

#define OMEGA 30.0f
#define P_TOTAL 50177
#define BATCH 16
#define N_PTS 32768
#define TILES_PER_CTA 4
#define CTAS_Y 64             // 64 * 4 * 128 = 32768 points per batch

#define WS 144                // padded K stride (fp16 elems): conflict-free v2 LDS
#define MS (128 * WS)         // 18432 elems per matrix
#define MATB (MS * 2)         // 36864 bytes per matrix

// small params per batch: W0[384]@0 b0@384 b1@512 b2@640 b3@768 Wo@896 bo@1024
__device__ __align__(16) float g_h2[BATCH * 256];
__device__ __align__(16) float g_small[BATCH][1040];
// per batch: W1, W2, W3 fp16, [n][k-interleaved] with row stride WS
__device__ __align__(16) unsigned short g_wblk[BATCH][3 * MS];

#define SM_SMALL (3 * MATB)                // 110592
#define SMEM_TOTAL (SM_SMALL + 1040 * 4)   // 114752

// ---------------------------------------------------------------------------
// helpers
// ---------------------------------------------------------------------------
__device__ __forceinline__ uint32_t smem_u32(const void* p) {
    uint32_t a;
    asm("{ .reg .u64 t; cvta.to.shared.u64 t, %1; cvt.u32.u64 %0, t; }"
        : "=r"(a) : "l"(p));
    return a;
}
__device__ __forceinline__ void lds64(uint32_t a, uint32_t& x, uint32_t& y) {
    asm volatile("ld.shared.v2.b32 {%0,%1}, [%2];" : "=r"(x), "=r"(y) : "r"(a));
}
__device__ __forceinline__ float ldsf(uint32_t a) {
    float v;
    asm volatile("ld.shared.f32 %0, [%1];" : "=f"(v) : "r"(a));
    return v;
}
__device__ __forceinline__ float2 lds2f(uint32_t a) {
    float2 v;
    asm volatile("ld.shared.v2.f32 {%0,%1}, [%2];" : "=f"(v.x), "=f"(v.y) : "r"(a));
    return v;
}
// D += A @ B^T, m16n8k16 fp16, fp32 accum (baseline PTX, works on sm_100)
__device__ __forceinline__ void mma_fp16(float* d, const uint32_t* a,
                                         uint32_t b0, uint32_t b1) {
    asm volatile(
        "mma.sync.aligned.m16n8k16.row.col.f32.f16.f16.f32 "
        "{%0,%1,%2,%3}, {%4,%5,%6,%7}, {%8,%9}, {%0,%1,%2,%3};"
        : "+f"(d[0]), "+f"(d[1]), "+f"(d[2]), "+f"(d[3])
        : "r"(a[0]), "r"(a[1]), "r"(a[2]), "r"(a[3]), "r"(b0), "r"(b1));
}
// fp16 hi/lo split of two fp32, packed fp16x2 (first value in low half)
__device__ __forceinline__ void split2h(float v0, float v1, uint32_t& hi, uint32_t& lo) {
    __half h0 = __float2half_rn(v0), h1 = __float2half_rn(v1);
    float r0 = v0 - __half2float(h0), r1 = v1 - __half2float(h1);
    __half l0 = __float2half_rn(r0), l1 = __float2half_rn(r1);
    hi = (uint32_t)__half_as_ushort(h0) | ((uint32_t)__half_as_ushort(h1) << 16);
    lo = (uint32_t)__half_as_ushort(l0) | ((uint32_t)__half_as_ushort(l1) << 16);
}

// ---------------------------------------------------------------------------
// K1: hypernet hidden chain, 1024 threads, 4 threads/neuron
// ---------------------------------------------------------------------------
__global__ void __launch_bounds__(1024) hyper_hidden_kernel(
    const float* __restrict__ t,
    const float* __restrict__ hW0, const float* __restrict__ hb0,
    const float* __restrict__ hW1, const float* __restrict__ hb1,
    const float* __restrict__ hW2, const float* __restrict__ hb2) {
    __shared__ float ts[8];
    __shared__ float h0[256];
    __shared__ float h1[256];
    int b = blockIdx.x;
    int tid = threadIdx.x;
    if (tid < 8) ts[tid] = t[b * 8 + tid];
    __syncthreads();

    if (tid < 256) {
        float acc = hb0[tid];
#pragma unroll
        for (int i = 0; i < 8; i++) acc += ts[i] * hW0[tid * 8 + i];
        h0[tid] = sinf(OMEGA * acc);
    }
    __syncthreads();

    int n = tid >> 2, part = tid & 3;
    {
        float acc = 0.f;
#pragma unroll 8
        for (int i = 0; i < 64; i++) {
            int c = part + i * 4;
            acc += h0[c] * hW1[n * 256 + c];
        }
        acc += __shfl_xor_sync(0xffffffffu, acc, 1);
        acc += __shfl_xor_sync(0xffffffffu, acc, 2);
        if (part == 0) h1[n] = sinf(OMEGA * (acc + hb1[n]));
    }
    __syncthreads();
    {
        float acc = 0.f;
#pragma unroll 8
        for (int i = 0; i < 64; i++) {
            int c = part + i * 4;
            acc += h1[c] * hW2[n * 256 + c];
        }
        acc += __shfl_xor_sync(0xffffffffu, acc, 1);
        acc += __shfl_xor_sync(0xffffffffu, acc, 2);
        if (part == 0) g_h2[b * 256 + n] = sinf(OMEGA * (acc + hb2[n]));
    }
}

// ---------------------------------------------------------------------------
// K2: params = h2 @ hWo^T + hbo, routed to g_small (fp32) and g_wblk (fp16,
// [n][k] with per-16-block k interleave so a B fragment is one v2 load)
// ---------------------------------------------------------------------------
__global__ void __launch_bounds__(256) hyper_out_kernel(
    const float* __restrict__ hWo, const float* __restrict__ hbo) {
    __shared__ float h2s[BATCH * 256];
    int tid = threadIdx.x;
    for (int i = tid; i < BATCH * 256; i += 256) h2s[i] = g_h2[i];
    __syncthreads();

    int j = blockIdx.x * 256 + tid;
    if (j >= P_TOTAL) return;

    float bias = hbo[j];
    float acc[BATCH];
#pragma unroll
    for (int b = 0; b < BATCH; b++) acc[b] = bias;

    const float4* w4 = reinterpret_cast<const float4*>(hWo + (size_t)j * 256);
#pragma unroll 4
    for (int c4 = 0; c4 < 64; c4++) {
        float4 w = w4[c4];
#pragma unroll
        for (int b = 0; b < BATCH; b++) {
            float4 h = *reinterpret_cast<const float4*>(&h2s[b * 256 + c4 * 4]);
            acc[b] += w.x * h.x + w.y * h.y + w.z * h.z + w.w * h.w;
        }
    }

    int layer = -1, r = 0, sidx = -1;
    if (j < 512)            sidx = j;                 // W0 + b0
    else if (j < 16896)   { layer = 0; r = j - 512; }
    else if (j < 17024)     sidx = 512 + (j - 16896); // b1
    else if (j < 33408)   { layer = 1; r = j - 17024; }
    else if (j < 33536)     sidx = 640 + (j - 33408); // b2
    else if (j < 49920)   { layer = 2; r = j - 33536; }
    else if (j < 50048)     sidx = 768 + (j - 49920); // b3
    else if (j < 50176)     sidx = 896 + (j - 50048); // Wo
    else                    sidx = 1024;              // bo

    if (layer >= 0) {
        int n = r >> 7, k = r & 127;
        int kb = k >> 4, kk = k & 15;
        // interleave within 16-block: [0,1,8,9, 2,3,10,11, 4,5,12,13, 6,7,14,15]
        int slot = ((kk & 7) >> 1) * 4 + (kk & 1) + ((kk >> 3) << 1);
        int idx = n * WS + kb * 16 + slot;
#pragma unroll
        for (int b = 0; b < BATCH; b++)
            g_wblk[b][layer * MS + idx] =
                __half_as_ushort(__float2half_rn(acc[b]));
    } else {
#pragma unroll
        for (int b = 0; b < BATCH; b++) g_small[b][sidx] = acc[b];
    }
}

// ---------------------------------------------------------------------------
// K3: warp-level fp16 MMA INR. 8 warps/CTA, 16 points/warp; activations chain
// through registers; A split hi/lo (exact), W single fp16; B loaded once and
// shared by both passes.
// ---------------------------------------------------------------------------
__global__ void __launch_bounds__(256, 1) inr_mma_kernel(
    const float* __restrict__ xt, float* __restrict__ out) {
    extern __shared__ char smem[];
    const uint32_t smb = smem_u32(smem);
    int tid = threadIdx.x, b = blockIdx.x;

    // weights + small params -> SMEM (linear float4 copy)
    {
        const float4* src = reinterpret_cast<const float4*>(g_wblk[b]);
        float4* dst = reinterpret_cast<float4*>(smem);
        for (int i = tid; i < (3 * MATB) / 16; i += 256) dst[i] = src[i];
        const float4* s2 = reinterpret_cast<const float4*>(g_small[b]);
        float4* d2 = reinterpret_cast<float4*>(smem + SM_SMALL);
        for (int i = tid; i < 260; i += 256) d2[i] = s2[i];
    }
    __syncthreads();

    const int lane = tid & 31, warp = tid >> 5;
    const int r = lane >> 2, q = lane & 3, qc = q * 2;
    const uint32_t smallb = smb + SM_SMALL;
    // B fragment base: row n = 8j + r, k-block i, pair q
    const uint32_t wlaneoff = (uint32_t)r * (WS * 2) + (uint32_t)q * 8;

    for (int tile = 0; tile < TILES_PER_CTA; tile++) {
        int pbase = (blockIdx.y * TILES_PER_CTA + tile) * 128 + warp * 16;
        int p0 = pbase + r;
        const float* xp = xt + ((size_t)b * N_PTS + p0) * 3;
        float x0 = xp[0], y0 = xp[1], z0 = xp[2];
        float x1 = xp[24], y1 = xp[25], z1 = xp[26];  // point p0 + 8

        // ---- layer 0: build A fragments (fp16 hi/lo) directly in registers
        uint32_t ahi[8][4], alo[8][4];
#pragma unroll
        for (int i = 0; i < 8; i++) {
#pragma unroll
            for (int h = 0; h < 2; h++) {
                int n0 = 16 * i + 8 * h + qc;
                float wa0 = ldsf(smallb + (n0 * 3 + 0) * 4);
                float wa1 = ldsf(smallb + (n0 * 3 + 1) * 4);
                float wa2 = ldsf(smallb + (n0 * 3 + 2) * 4);
                float ba  = ldsf(smallb + (384 + n0) * 4);
                float wb0 = ldsf(smallb + (n0 * 3 + 3) * 4);
                float wb1 = ldsf(smallb + (n0 * 3 + 4) * 4);
                float wb2 = ldsf(smallb + (n0 * 3 + 5) * 4);
                float bb  = ldsf(smallb + (385 + n0) * 4);
                float vA0 = __sinf(OMEGA * (wa0 * x0 + wa1 * y0 + wa2 * z0 + ba));
                float vB0 = __sinf(OMEGA * (wb0 * x0 + wb1 * y0 + wb2 * z0 + bb));
                float vA1 = __sinf(OMEGA * (wa0 * x1 + wa1 * y1 + wa2 * z1 + ba));
                float vB1 = __sinf(OMEGA * (wb0 * x1 + wb1 * y1 + wb2 * z1 + bb));
                split2h(vA0, vB0, ahi[i][2 * h], alo[i][2 * h]);
                split2h(vA1, vB1, ahi[i][2 * h + 1], alo[i][2 * h + 1]);
            }
        }

        float part0 = 0.f, part1 = 0.f;
#pragma unroll 1
        for (int L = 0; L < 3; L++) {
            float acc[16][4];
#pragma unroll
            for (int j = 0; j < 16; j++) {
                acc[j][0] = 0.f; acc[j][1] = 0.f; acc[j][2] = 0.f; acc[j][3] = 0.f;
            }
            uint32_t wb_ = smb + (uint32_t)L * MATB + wlaneoff;
            // B loaded once per (i,j); both hi and lo passes consume it.
#pragma unroll
            for (int i = 0; i < 8; i++) {
                uint32_t koff = (uint32_t)i * 32;
#pragma unroll
                for (int jj = 0; jj < 8; jj++) {
                    uint32_t a0 = wb_ + (uint32_t)(2 * jj) * (8 * WS * 2) + koff;
                    uint32_t b00, b01, b10, b11;
                    lds64(a0, b00, b01);
                    lds64(a0 + 8 * WS * 2, b10, b11);
                    mma_fp16(acc[2 * jj],     ahi[i], b00, b01);
                    mma_fp16(acc[2 * jj + 1], ahi[i], b10, b11);
                    mma_fp16(acc[2 * jj],     alo[i], b00, b01);
                    mma_fp16(acc[2 * jj + 1], alo[i], b10, b11);
                }
            }

            if (L < 2) {
                // epilogue: bias + sin + hi/lo split -> next-layer A fragments
                uint32_t biasb = smallb + (uint32_t)(512 + 128 * L) * 4;
#pragma unroll
                for (int j = 0; j < 16; j++) {
                    float2 bs = lds2f(biasb + (8 * j + qc) * 4);
                    float s0 = __sinf(OMEGA * (acc[j][0] + bs.x));
                    float s1 = __sinf(OMEGA * (acc[j][1] + bs.y));
                    float s2 = __sinf(OMEGA * (acc[j][2] + bs.x));
                    float s3 = __sinf(OMEGA * (acc[j][3] + bs.y));
                    split2h(s0, s1, ahi[j >> 1][(j & 1) * 2], alo[j >> 1][(j & 1) * 2]);
                    split2h(s2, s3, ahi[j >> 1][(j & 1) * 2 + 1], alo[j >> 1][(j & 1) * 2 + 1]);
                }
            } else {
                // final epilogue fused with output dot product
                uint32_t biasb = smallb + 768 * 4;
                uint32_t wob   = smallb + 896 * 4;
#pragma unroll
                for (int j = 0; j < 16; j++) {
                    float2 bs = lds2f(biasb + (8 * j + qc) * 4);
                    float2 wo = lds2f(wob + (8 * j + qc) * 4);
                    part0 += __sinf(OMEGA * (acc[j][0] + bs.x)) * wo.x
                           + __sinf(OMEGA * (acc[j][1] + bs.y)) * wo.y;
                    part1 += __sinf(OMEGA * (acc[j][2] + bs.x)) * wo.x
                           + __sinf(OMEGA * (acc[j][3] + bs.y)) * wo.y;
                }
            }
        }

        part0 += __shfl_xor_sync(0xffffffffu, part0, 1);
        part0 += __shfl_xor_sync(0xffffffffu, part0, 2);
        part1 += __shfl_xor_sync(0xffffffffu, part1, 1);
        part1 += __shfl_xor_sync(0xffffffffu, part1, 2);
        if ((lane & 3) == 0) {
            float bo = ldsf(smallb + 1024 * 4);
            out[(size_t)b * N_PTS + p0]     = part0 + bo;
            out[(size_t)b * N_PTS + p0 + 8] = part1 + bo;
        }
    }
}

// ---------------------------------------------------------------------------
extern "C" void kernel_launch(void* const* d_in, const int* in_sizes, int n_in,
                              void* d_out, int out_size) {
    const float* t   = (const float*)d_in[0];
    const float* xt  = (const float*)d_in[1];
    const float* hW0 = (const float*)d_in[2];
    const float* hb0 = (const float*)d_in[3];
    const float* hW1 = (const float*)d_in[4];
    const float* hb1 = (const float*)d_in[5];
    const float* hW2 = (const float*)d_in[6];
    const float* hb2 = (const float*)d_in[7];
    const float* hWo = (const float*)d_in[8];
    const float* hbo = (const float*)d_in[9];
    float* out = (float*)d_out;

    hyper_hidden_kernel<<<BATCH, 1024>>>(t, hW0, hb0, hW1, hb1, hW2, hb2);
    hyper_out_kernel<<<(P_TOTAL + 255) / 256, 256>>>(hWo, hbo);

    cudaFuncSetAttribute(inr_mma_kernel,
                         cudaFuncAttributeMaxDynamicSharedMemorySize, SMEM_TOTAL);
    inr_mma_kernel<<<dim3(BATCH, CTAS_Y), 256, SMEM_TOTAL>>>(xt, out);
}

// round 11
// speedup vs baseline: 6.2484x; 1.4524x over previous
#include <cuda_runtime.h>
#include <cuda_fp16.h>
#include <cstdint>

#define OMEGA 30.0f
#define P_TOTAL 50177
#define BATCH 16
#define N_PTS 32768
#define TILES_PER_CTA 4
#define CTAS_Y 64             // 64 * 4 * 128 = 32768 points per batch

#define WS 144                // padded K stride (fp16 elems): conflict-free v2 LDS
#define MS (128 * WS)         // 18432 elems per matrix
#define MATB (MS * 2)         // 36864 bytes per matrix

// small params per batch: W0[384]@0 b0@384 b1@512 b2@640 b3@768 Wo@896 bo@1024
__device__ __align__(16) float g_h2[BATCH * 256];
__device__ __align__(16) float g_small[BATCH][1040];
// per batch: W1, W2, W3 fp16, [n][k-interleaved] with row stride WS
__device__ __align__(16) unsigned short g_wblk[BATCH][3 * MS];

#define SMEM_TOTAL (3 * MATB)              // 110592 -> 2 CTAs/SM

// ---------------------------------------------------------------------------
// helpers
// ---------------------------------------------------------------------------
__device__ __forceinline__ uint32_t smem_u32(const void* p) {
    uint32_t a;
    asm("{ .reg .u64 t; cvta.to.shared.u64 t, %1; cvt.u32.u64 %0, t; }"
        : "=r"(a) : "l"(p));
    return a;
}
__device__ __forceinline__ void lds64(uint32_t a, uint32_t& x, uint32_t& y) {
    asm volatile("ld.shared.v2.b32 {%0,%1}, [%2];" : "=r"(x), "=r"(y) : "r"(a));
}
// D += A @ B^T, m16n8k16 fp16, fp32 accum (baseline PTX, works on sm_100)
__device__ __forceinline__ void mma_fp16(float* d, const uint32_t* a,
                                         uint32_t b0, uint32_t b1) {
    asm volatile(
        "mma.sync.aligned.m16n8k16.row.col.f32.f16.f16.f32 "
        "{%0,%1,%2,%3}, {%4,%5,%6,%7}, {%8,%9}, {%0,%1,%2,%3};"
        : "+f"(d[0]), "+f"(d[1]), "+f"(d[2]), "+f"(d[3])
        : "r"(a[0]), "r"(a[1]), "r"(a[2]), "r"(a[3]), "r"(b0), "r"(b1));
}
// two fp32 -> packed fp16x2 (first value in low half)
__device__ __forceinline__ uint32_t cvt2h(float v0, float v1) {
    __half h0 = __float2half_rn(v0), h1 = __float2half_rn(v1);
    return (uint32_t)__half_as_ushort(h0) | ((uint32_t)__half_as_ushort(h1) << 16);
}

// ---------------------------------------------------------------------------
// K1: hypernet hidden chain, 1024 threads, 4 threads/neuron
// ---------------------------------------------------------------------------
__global__ void __launch_bounds__(1024) hyper_hidden_kernel(
    const float* __restrict__ t,
    const float* __restrict__ hW0, const float* __restrict__ hb0,
    const float* __restrict__ hW1, const float* __restrict__ hb1,
    const float* __restrict__ hW2, const float* __restrict__ hb2) {
    __shared__ float ts[8];
    __shared__ float h0[256];
    __shared__ float h1[256];
    int b = blockIdx.x;
    int tid = threadIdx.x;
    if (tid < 8) ts[tid] = t[b * 8 + tid];
    __syncthreads();

    if (tid < 256) {
        float acc = hb0[tid];
#pragma unroll
        for (int i = 0; i < 8; i++) acc += ts[i] * hW0[tid * 8 + i];
        h0[tid] = sinf(OMEGA * acc);
    }
    __syncthreads();

    int n = tid >> 2, part = tid & 3;
    {
        float acc = 0.f;
#pragma unroll 8
        for (int i = 0; i < 64; i++) {
            int c = part + i * 4;
            acc += h0[c] * hW1[n * 256 + c];
        }
        acc += __shfl_xor_sync(0xffffffffu, acc, 1);
        acc += __shfl_xor_sync(0xffffffffu, acc, 2);
        if (part == 0) h1[n] = sinf(OMEGA * (acc + hb1[n]));
    }
    __syncthreads();
    {
        float acc = 0.f;
#pragma unroll 8
        for (int i = 0; i < 64; i++) {
            int c = part + i * 4;
            acc += h1[c] * hW2[n * 256 + c];
        }
        acc += __shfl_xor_sync(0xffffffffu, acc, 1);
        acc += __shfl_xor_sync(0xffffffffu, acc, 2);
        if (part == 0) g_h2[b * 256 + n] = sinf(OMEGA * (acc + hb2[n]));
    }
}

// ---------------------------------------------------------------------------
// K2: params = h2 @ hWo^T + hbo, routed to g_small (fp32) and g_wblk (fp16,
// [n][k] with per-16-block k interleave so a B fragment is one v2 load)
// ---------------------------------------------------------------------------
__global__ void __launch_bounds__(256) hyper_out_kernel(
    const float* __restrict__ hWo, const float* __restrict__ hbo) {
    __shared__ float h2s[BATCH * 256];
    int tid = threadIdx.x;
    for (int i = tid; i < BATCH * 256; i += 256) h2s[i] = g_h2[i];
    __syncthreads();

    int j = blockIdx.x * 256 + tid;
    if (j >= P_TOTAL) return;

    float bias = hbo[j];
    float acc[BATCH];
#pragma unroll
    for (int b = 0; b < BATCH; b++) acc[b] = bias;

    const float4* w4 = reinterpret_cast<const float4*>(hWo + (size_t)j * 256);
#pragma unroll 4
    for (int c4 = 0; c4 < 64; c4++) {
        float4 w = w4[c4];
#pragma unroll
        for (int b = 0; b < BATCH; b++) {
            float4 h = *reinterpret_cast<const float4*>(&h2s[b * 256 + c4 * 4]);
            acc[b] += w.x * h.x + w.y * h.y + w.z * h.z + w.w * h.w;
        }
    }

    int layer = -1, r = 0, sidx = -1;
    if (j < 512)            sidx = j;                 // W0 + b0
    else if (j < 16896)   { layer = 0; r = j - 512; }
    else if (j < 17024)     sidx = 512 + (j - 16896); // b1
    else if (j < 33408)   { layer = 1; r = j - 17024; }
    else if (j < 33536)     sidx = 640 + (j - 33408); // b2
    else if (j < 49920)   { layer = 2; r = j - 33536; }
    else if (j < 50048)     sidx = 768 + (j - 49920); // b3
    else if (j < 50176)     sidx = 896 + (j - 50048); // Wo
    else                    sidx = 1024;              // bo

    if (layer >= 0) {
        int n = r >> 7, k = r & 127;
        int kb = k >> 4, kk = k & 15;
        // interleave within 16-block: [0,1,8,9, 2,3,10,11, 4,5,12,13, 6,7,14,15]
        int slot = ((kk & 7) >> 1) * 4 + (kk & 1) + ((kk >> 3) << 1);
        int idx = n * WS + kb * 16 + slot;
#pragma unroll
        for (int b = 0; b < BATCH; b++)
            g_wblk[b][layer * MS + idx] =
                __half_as_ushort(__float2half_rn(acc[b]));
    } else {
#pragma unroll
        for (int b = 0; b < BATCH; b++) g_small[b][sidx] = acc[b];
    }
}

// ---------------------------------------------------------------------------
// K3: warp-level fp16 MMA INR, single pass (A fp16, W fp16), 2 CTAs/SM.
// 8 warps/CTA, 16 points/warp; activations chain through registers.
// Small params read via __ldg (L1-resident broadcast), weights in SMEM.
// ---------------------------------------------------------------------------
__global__ void __launch_bounds__(256, 2) inr_mma_kernel(
    const float* __restrict__ xt, float* __restrict__ out) {
    extern __shared__ char smem[];
    const uint32_t smb = smem_u32(smem);
    int tid = threadIdx.x, b = blockIdx.x;

    // weights -> SMEM (linear float4 copy)
    {
        const float4* src = reinterpret_cast<const float4*>(g_wblk[b]);
        float4* dst = reinterpret_cast<float4*>(smem);
        for (int i = tid; i < (3 * MATB) / 16; i += 256) dst[i] = src[i];
    }
    __syncthreads();

    const int lane = tid & 31, warp = tid >> 5;
    const int r = lane >> 2, q = lane & 3, qc = q * 2;
    const float* sp = g_small[b];
    // B fragment base: row n = 8j + r, k-block i, pair q
    const uint32_t wlaneoff = (uint32_t)r * (WS * 2) + (uint32_t)q * 8;

    for (int tile = 0; tile < TILES_PER_CTA; tile++) {
        int pbase = (blockIdx.y * TILES_PER_CTA + tile) * 128 + warp * 16;
        int p0 = pbase + r;
        const float* xp = xt + ((size_t)b * N_PTS + p0) * 3;
        float x0 = xp[0], y0 = xp[1], z0 = xp[2];
        float x1 = xp[24], y1 = xp[25], z1 = xp[26];  // point p0 + 8

        // ---- layer 0: build A fragments (fp16) directly in registers
        uint32_t afr[8][4];
#pragma unroll
        for (int i = 0; i < 8; i++) {
#pragma unroll
            for (int h = 0; h < 2; h++) {
                int n0 = 16 * i + 8 * h + qc;
                float wa0 = __ldg(sp + n0 * 3 + 0);
                float wa1 = __ldg(sp + n0 * 3 + 1);
                float wa2 = __ldg(sp + n0 * 3 + 2);
                float ba  = __ldg(sp + 384 + n0);
                float wb0 = __ldg(sp + n0 * 3 + 3);
                float wb1 = __ldg(sp + n0 * 3 + 4);
                float wb2 = __ldg(sp + n0 * 3 + 5);
                float bb  = __ldg(sp + 385 + n0);
                float vA0 = __sinf(OMEGA * (wa0 * x0 + wa1 * y0 + wa2 * z0 + ba));
                float vB0 = __sinf(OMEGA * (wb0 * x0 + wb1 * y0 + wb2 * z0 + bb));
                float vA1 = __sinf(OMEGA * (wa0 * x1 + wa1 * y1 + wa2 * z1 + ba));
                float vB1 = __sinf(OMEGA * (wb0 * x1 + wb1 * y1 + wb2 * z1 + bb));
                afr[i][2 * h]     = cvt2h(vA0, vB0);
                afr[i][2 * h + 1] = cvt2h(vA1, vB1);
            }
        }

        float part0 = 0.f, part1 = 0.f;
#pragma unroll 1
        for (int L = 0; L < 3; L++) {
            float acc[16][4];
#pragma unroll
            for (int j = 0; j < 16; j++) {
                acc[j][0] = 0.f; acc[j][1] = 0.f; acc[j][2] = 0.f; acc[j][3] = 0.f;
            }
            uint32_t wb_ = smb + (uint32_t)L * MATB + wlaneoff;
#pragma unroll
            for (int i = 0; i < 8; i++) {
                uint32_t koff = (uint32_t)i * 32;
#pragma unroll
                for (int jj = 0; jj < 8; jj++) {
                    uint32_t a0 = wb_ + (uint32_t)(2 * jj) * (8 * WS * 2) + koff;
                    uint32_t b00, b01, b10, b11;
                    lds64(a0, b00, b01);
                    lds64(a0 + 8 * WS * 2, b10, b11);
                    mma_fp16(acc[2 * jj],     afr[i], b00, b01);
                    mma_fp16(acc[2 * jj + 1], afr[i], b10, b11);
                }
            }

            if (L < 2) {
                // epilogue: bias + sin + fp16 cvt -> next-layer A fragments
                const float* biasp = sp + 512 + 128 * L;
#pragma unroll
                for (int j = 0; j < 16; j++) {
                    float bx = __ldg(biasp + 8 * j + qc);
                    float by = __ldg(biasp + 8 * j + qc + 1);
                    float s0 = __sinf(OMEGA * (acc[j][0] + bx));
                    float s1 = __sinf(OMEGA * (acc[j][1] + by));
                    float s2 = __sinf(OMEGA * (acc[j][2] + bx));
                    float s3 = __sinf(OMEGA * (acc[j][3] + by));
                    afr[j >> 1][(j & 1) * 2]     = cvt2h(s0, s1);
                    afr[j >> 1][(j & 1) * 2 + 1] = cvt2h(s2, s3);
                }
            } else {
                // final epilogue fused with output dot product
                const float* biasp = sp + 768;
                const float* wop   = sp + 896;
#pragma unroll
                for (int j = 0; j < 16; j++) {
                    float bx = __ldg(biasp + 8 * j + qc);
                    float by = __ldg(biasp + 8 * j + qc + 1);
                    float wx = __ldg(wop + 8 * j + qc);
                    float wy = __ldg(wop + 8 * j + qc + 1);
                    part0 += __sinf(OMEGA * (acc[j][0] + bx)) * wx
                           + __sinf(OMEGA * (acc[j][1] + by)) * wy;
                    part1 += __sinf(OMEGA * (acc[j][2] + bx)) * wx
                           + __sinf(OMEGA * (acc[j][3] + by)) * wy;
                }
            }
        }

        part0 += __shfl_xor_sync(0xffffffffu, part0, 1);
        part0 += __shfl_xor_sync(0xffffffffu, part0, 2);
        part1 += __shfl_xor_sync(0xffffffffu, part1, 1);
        part1 += __shfl_xor_sync(0xffffffffu, part1, 2);
        if ((lane & 3) == 0) {
            float bo = __ldg(sp + 1024);
            out[(size_t)b * N_PTS + p0]     = part0 + bo;
            out[(size_t)b * N_PTS + p0 + 8] = part1 + bo;
        }
    }
}

// ---------------------------------------------------------------------------
extern "C" void kernel_launch(void* const* d_in, const int* in_sizes, int n_in,
                              void* d_out, int out_size) {
    const float* t   = (const float*)d_in[0];
    const float* xt  = (const float*)d_in[1];
    const float* hW0 = (const float*)d_in[2];
    const float* hb0 = (const float*)d_in[3];
    const float* hW1 = (const float*)d_in[4];
    const float* hb1 = (const float*)d_in[5];
    const float* hW2 = (const float*)d_in[6];
    const float* hb2 = (const float*)d_in[7];
    const float* hWo = (const float*)d_in[8];
    const float* hbo = (const float*)d_in[9];
    float* out = (float*)d_out;

    hyper_hidden_kernel<<<BATCH, 1024>>>(t, hW0, hb0, hW1, hb1, hW2, hb2);
    hyper_out_kernel<<<(P_TOTAL + 255) / 256, 256>>>(hWo, hbo);

    cudaFuncSetAttribute(inr_mma_kernel,
                         cudaFuncAttributeMaxDynamicSharedMemorySize, SMEM_TOTAL);
    inr_mma_kernel<<<dim3(BATCH, CTAS_Y), 256, SMEM_TOTAL>>>(xt, out);
}